// round 13
// baseline (speedup 1.0000x reference)
#include <cuda_runtime.h>
#include <math.h>

// Problem constants (fixed by reference)
#define B_    2
#define S_    2048
#define H_    288
#define NH_   18
#define D_    16
#define M_TOT (B_ * S_)                  // 4096
#define QKV_ELEMS (B_ * NH_ * S_ * D_)   // 1,179,648
#define PART_Q (36 * 2048)               // queries across all (b,h)
#define NSPLIT 4                         // attention split-K ways (4 is load-bearing)

typedef unsigned long long u64;

// ---------------- scratch (device globals; no allocation allowed) -----------
__device__ float g_q[QKV_ELEMS];
__device__ float g_k[QKV_ELEMS];
__device__ float g_v[QKV_ELEMS];
__device__ float g_ao[M_TOT * H_];
__device__ float g_part[3 * M_TOT * H_];        // split-K partials for out proj
__device__ float g_po[NSPLIT * PART_Q * 16];    // attention split-K o partials
__device__ float g_pl[NSPLIT * PART_Q];         // attention split-K l partials

// exact 10000^(-d/8) = 10^(-d/2) table for RoPE
__constant__ float c_inv[8] = {
    1.0f, 0.31622776601683794f, 0.1f, 0.031622776601683794f,
    0.01f, 0.0031622776601683794f, 0.001f, 0.00031622776601683794f
};

// 0.25 * log2(e): folds 1/sqrt(D) and the exp->exp2 conversion into q
#define QSCALE 0.36067376022224085f

// ---------------- f32x2 helpers (Blackwell packed fp32) ---------------------
__device__ __forceinline__ u64 pk2(float lo, float hi) {
    u64 r;
    asm("mov.b64 %0, {%1, %2};" : "=l"(r) : "f"(lo), "f"(hi));
    return r;
}
__device__ __forceinline__ void unpk2(u64 a, float& lo, float& hi) {
    asm("mov.b64 {%0, %1}, %2;" : "=f"(lo), "=f"(hi) : "l"(a));
}
__device__ __forceinline__ u64 fma2(u64 a, u64 b, u64 c) {
    u64 d;
    asm("fma.rn.f32x2 %0, %1, %2, %3;" : "=l"(d) : "l"(a), "l"(b), "l"(c));
    return d;
}
__device__ __forceinline__ u64 mul2(u64 a, u64 b) {
    u64 d;
    asm("mul.rn.f32x2 %0, %1, %2;" : "=l"(d) : "l"(a), "l"(b));
    return d;
}
__device__ __forceinline__ u64 add2(u64 a, u64 b) {
    u64 d;
    asm("add.rn.f32x2 %0, %1, %2;" : "=l"(d) : "l"(a), "l"(b));
    return d;
}
// Guaranteed single MUFU.EX2.
__device__ __forceinline__ float ex2(float x) {
    float y;
    asm("ex2.approx.ftz.f32 %0, %1;" : "=f"(y) : "f"(x));
    return y;
}

// =============================================================================
// k-packed GEMM core: 64(m) x 96(n) block tile, 256 threads, 4m x 6n/thread.
// PAD_=34: stride-34 u64 reads map to bank 2*tc -> conflict-free (R10-proven).
// =============================================================================
#define PAD_ 34

template<int NCHUNKS>
__device__ __forceinline__ void gemm_core(
    const float* __restrict__ X, const float* __restrict__ W,
    int m0, int n0, int kbase, int tid,
    float (&Xs)[2][64][PAD_], float (&Ws)[2][96][PAD_],
    u64 (&acc)[4][6])
{
    const int tr4 = (tid >> 4) * 4;
    const int tc  = tid & 15;

    const int lr = tid >> 3;
    const int lq = (tid & 7) << 2;

    const float* Xp0 = X + (size_t)(m0 + lr)      * 288 + kbase + lq;
    const float* Xp1 = X + (size_t)(m0 + lr + 32) * 288 + kbase + lq;
    const float* Wp0 = W + (size_t)(n0 + lr)      * 288 + kbase + lq;
    const float* Wp1 = W + (size_t)(n0 + lr + 32) * 288 + kbase + lq;
    const float* Wp2 = W + (size_t)(n0 + lr + 64) * 288 + kbase + lq;

    {
        float4 a = *(const float4*)Xp0;
        float4 b = *(const float4*)Xp1;
        float4 c = *(const float4*)Wp0;
        float4 d = *(const float4*)Wp1;
        float4 e = *(const float4*)Wp2;
        *(float2*)&Xs[0][lr     ][lq    ] = make_float2(a.x, a.y);
        *(float2*)&Xs[0][lr     ][lq + 2] = make_float2(a.z, a.w);
        *(float2*)&Xs[0][lr + 32][lq    ] = make_float2(b.x, b.y);
        *(float2*)&Xs[0][lr + 32][lq + 2] = make_float2(b.z, b.w);
        *(float2*)&Ws[0][lr     ][lq    ] = make_float2(c.x, c.y);
        *(float2*)&Ws[0][lr     ][lq + 2] = make_float2(c.z, c.w);
        *(float2*)&Ws[0][lr + 32][lq    ] = make_float2(d.x, d.y);
        *(float2*)&Ws[0][lr + 32][lq + 2] = make_float2(d.z, d.w);
        *(float2*)&Ws[0][lr + 64][lq    ] = make_float2(e.x, e.y);
        *(float2*)&Ws[0][lr + 64][lq + 2] = make_float2(e.z, e.w);
    }

    for (int it = 0; it < NCHUNKS; it++) {
        const int buf = it & 1;
        float4 a, b, c, d, e;
        if (it < NCHUNKS - 1) {
            const int ko = (it + 1) * 32;
            a = *(const float4*)(Xp0 + ko);
            b = *(const float4*)(Xp1 + ko);
            c = *(const float4*)(Wp0 + ko);
            d = *(const float4*)(Wp1 + ko);
            e = *(const float4*)(Wp2 + ko);
        }
        __syncthreads();
#pragma unroll
        for (int kk = 0; kk < 16; kk++) {
            u64 x[4], w[6];
#pragma unroll
            for (int i = 0; i < 4; i++)
                x[i] = *(const u64*)&Xs[buf][tr4 + i][2 * kk];
#pragma unroll
            for (int j = 0; j < 6; j++)
                w[j] = *(const u64*)&Ws[buf][tc + 16 * j][2 * kk];
#pragma unroll
            for (int i = 0; i < 4; i++)
#pragma unroll
                for (int j = 0; j < 6; j++)
                    acc[i][j] = fma2(x[i], w[j], acc[i][j]);
        }
        if (it < NCHUNKS - 1) {
            const int nb = buf ^ 1;
            *(float2*)&Xs[nb][lr     ][lq    ] = make_float2(a.x, a.y);
            *(float2*)&Xs[nb][lr     ][lq + 2] = make_float2(a.z, a.w);
            *(float2*)&Xs[nb][lr + 32][lq    ] = make_float2(b.x, b.y);
            *(float2*)&Xs[nb][lr + 32][lq + 2] = make_float2(b.z, b.w);
            *(float2*)&Ws[nb][lr     ][lq    ] = make_float2(c.x, c.y);
            *(float2*)&Ws[nb][lr     ][lq + 2] = make_float2(c.z, c.w);
            *(float2*)&Ws[nb][lr + 32][lq    ] = make_float2(d.x, d.y);
            *(float2*)&Ws[nb][lr + 32][lq + 2] = make_float2(d.z, d.w);
            *(float2*)&Ws[nb][lr + 64][lq    ] = make_float2(e.x, e.y);
            *(float2*)&Ws[nb][lr + 64][lq + 2] = make_float2(e.z, e.w);
        }
    }
}

// =============================================================================
// Kernel 1: fused QKV projection with scatter epilogue into [b,h,s,d].
// =============================================================================
__global__ __launch_bounds__(256) void gemm_qkv_kernel(
    const float* __restrict__ X,
    const float* __restrict__ Wq,
    const float* __restrict__ Wk,
    const float* __restrict__ Wv)
{
    __shared__ __align__(16) float Xs[2][64][PAD_];
    __shared__ __align__(16) float Ws[2][96][PAD_];

    const int m0 = blockIdx.x * 64;
    const int cb = blockIdx.y;
    const float* __restrict__ W = (cb < 3) ? Wq : (cb < 6 ? Wk : Wv);
    float* dst = (cb < 3) ? g_q : (cb < 6 ? g_k : g_v);
    const int n0 = (cb % 3) * 96;
    const int tid = threadIdx.x;

    u64 acc[4][6];
#pragma unroll
    for (int i = 0; i < 4; i++)
#pragma unroll
        for (int j = 0; j < 6; j++) acc[i][j] = 0ULL;

    gemm_core<9>(X, W, m0, n0, 0, tid, Xs, Ws, acc);

    const int tr4 = (tid >> 4) * 4, tc = tid & 15;
#pragma unroll
    for (int i = 0; i < 4; i++) {
        int m = m0 + tr4 + i;
        int b = m >> 11, s = m & 2047;
#pragma unroll
        for (int j = 0; j < 6; j++) {
            float lo, hi; unpk2(acc[i][j], lo, hi);
            int c = n0 + tc + 16 * j;
            int h = c >> 4, d = c & 15;
            dst[(((size_t)(b * NH_ + h)) * S_ + s) * D_ + d] = lo + hi;
        }
    }
}

// =============================================================================
// Kernel 2: RoPE in-place; folds (1/sqrt(D)) * log2(e) into q.
// =============================================================================
__global__ void rope_kernel()
{
    int idx = blockIdx.x * blockDim.x + threadIdx.x;
    const int total = 2 * B_ * NH_ * S_ * 8;
    if (idx >= total) return;
    int d = idx & 7;
    int s = (idx >> 3) & (S_ - 1);
    int v = idx >> 14;
    bool isq = v < 36;
    float* base = (isq ? g_q : g_k) + (((size_t)(v % 36)) * S_ + s) * D_;
    float f = (float)s * c_inv[d];
    float sn, cs;
    sincosf(f, &sn, &cs);
    float scale = isq ? QSCALE : 1.0f;
    float x0 = base[d];
    float x1 = base[d + 8];
    base[d]     = (x0 * cs - x1 * sn) * scale;
    base[d + 8] = (x1 * cs + x0 * sn) * scale;
}

// =============================================================================
// Kernel 3: causal attention, split-K x4, double-buffered K/V,
// WARP-uniform mask specialization:
//   tile kt==2p   : warps 0-1 masked-A, warps 2-3 provably-unmasked A
//   tile kt==2p+1 : warps 0-1 A fully dead -> B-only; warps 2-3 masked-A
//   tile ntB-2    : warps 0-1 masked-B, warps 2-3 unmasked
//   tile ntB-1    : warps 0-1 SKIP ENTIRELY; warps 2-3 masked-B
// =============================================================================
template<bool BOTH, bool MASK>
__device__ __forceinline__ void attn_inner(
    const ulonglong2* __restrict__ Ks2, const ulonglong2* __restrict__ Vs2,
    const u64 (&qA)[8], const u64 (&qB)[8],
    u64 (&oA)[8], u64 (&oB)[8],
    float& lA, float& lB, int jthrA, int jthrB)
{
#pragma unroll 4
    for (int j = 0; j < 64; j++) {
        ulonglong2 k0 = Ks2[j * 4 + 0];
        ulonglong2 k1 = Ks2[j * 4 + 1];
        ulonglong2 k2 = Ks2[j * 4 + 2];
        ulonglong2 k3 = Ks2[j * 4 + 3];

        u64 b0 = mul2(qB[0], k0.x), b1 = mul2(qB[1], k0.y);
        b0 = fma2(qB[2], k1.x, b0); b1 = fma2(qB[3], k1.y, b1);
        b0 = fma2(qB[4], k2.x, b0); b1 = fma2(qB[5], k2.y, b1);
        b0 = fma2(qB[6], k3.x, b0); b1 = fma2(qB[7], k3.y, b1);
        u64 bs = add2(b0, b1);
        float blo, bhi; unpk2(bs, blo, bhi);
        float sB = blo + bhi;
        float pB;
        if (!BOTH && MASK) pB = (j <= jthrB) ? ex2(sB) : 0.0f;
        else               pB = ex2(sB);
        lB += pB;

        float pA = 0.0f;
        if (BOTH) {
            u64 a0 = mul2(qA[0], k0.x), a1 = mul2(qA[1], k0.y);
            a0 = fma2(qA[2], k1.x, a0); a1 = fma2(qA[3], k1.y, a1);
            a0 = fma2(qA[4], k2.x, a0); a1 = fma2(qA[5], k2.y, a1);
            a0 = fma2(qA[6], k3.x, a0); a1 = fma2(qA[7], k3.y, a1);
            u64 as = add2(a0, a1);
            float alo, ahi; unpk2(as, alo, ahi);
            float sA = alo + ahi;
            if (MASK) pA = (j <= jthrA) ? ex2(sA) : 0.0f;
            else      pA = ex2(sA);
            lA += pA;
        }

        ulonglong2 v0 = Vs2[j * 4 + 0];
        ulonglong2 v1 = Vs2[j * 4 + 1];
        ulonglong2 v2 = Vs2[j * 4 + 2];
        ulonglong2 v3 = Vs2[j * 4 + 3];

        u64 pB2 = pk2(pB, pB);
        oB[0] = fma2(pB2, v0.x, oB[0]); oB[1] = fma2(pB2, v0.y, oB[1]);
        oB[2] = fma2(pB2, v1.x, oB[2]); oB[3] = fma2(pB2, v1.y, oB[3]);
        oB[4] = fma2(pB2, v2.x, oB[4]); oB[5] = fma2(pB2, v2.y, oB[5]);
        oB[6] = fma2(pB2, v3.x, oB[6]); oB[7] = fma2(pB2, v3.y, oB[7]);
        if (BOTH) {
            u64 pA2 = pk2(pA, pA);
            oA[0] = fma2(pA2, v0.x, oA[0]); oA[1] = fma2(pA2, v0.y, oA[1]);
            oA[2] = fma2(pA2, v1.x, oA[2]); oA[3] = fma2(pA2, v1.y, oA[3]);
            oA[4] = fma2(pA2, v2.x, oA[4]); oA[5] = fma2(pA2, v2.y, oA[5]);
            oA[6] = fma2(pA2, v3.x, oA[6]); oA[7] = fma2(pA2, v3.y, oA[7]);
        }
    }
}

__global__ __launch_bounds__(128) void attn_kernel()
{
    __shared__ __align__(16) float Ks[2][64 * 16];
    __shared__ __align__(16) float Vs[2][64 * 16];

    const int bh   = blockIdx.y;                     // 0..35
    const int p    = blockIdx.x;                     // 0..7 (pair index)
    const int half = blockIdx.z;                     // 0..NSPLIT-1 (tile residue)
    const int tid  = threadIdx.x;
    const int wid  = tid >> 5;                       // warp 0..3
    const int qa = p * 128 + tid;                    // short query
    const int qb = (15 - p) * 128 + tid;             // long query
    const int ntA = 2 * p + 2;
    const int ntB = 32 - 2 * p;

    const float* qpa = g_q + ((size_t)bh * S_ + qa) * D_;
    const float* qpb = g_q + ((size_t)bh * S_ + qb) * D_;
    u64 qA[8], qB[8];
#pragma unroll
    for (int c = 0; c < 8; c++) {
        qA[c] = *(const u64*)(qpa + 2 * c);          // pre-scaled in rope
        qB[c] = *(const u64*)(qpb + 2 * c);
    }
    u64 oA[8], oB[8];
#pragma unroll
    for (int i = 0; i < 8; i++) { oA[i] = 0ULL; oB[i] = 0ULL; }
    float lA = 0.0f, lB = 0.0f;

    const float* kbase = g_k + (size_t)bh * S_ * D_;
    const float* vbase = g_v + (size_t)bh * S_ * D_;

    // ---- prologue: first tile into buffer 0 ---------------------------------
    {
        const float4* ks = (const float4*)(kbase + (size_t)half * 64 * D_);
        const float4* vs = (const float4*)(vbase + (size_t)half * 64 * D_);
        float4 ka = ks[tid], kb = ks[tid + 128];
        float4 va = vs[tid], vb = vs[tid + 128];
        ((float4*)Ks[0])[tid]       = ka;
        ((float4*)Ks[0])[tid + 128] = kb;
        ((float4*)Vs[0])[tid]       = va;
        ((float4*)Vs[0])[tid + 128] = vb;
    }

    int buf = 0;
    for (int kt = half; kt < ntB; kt += NSPLIT, buf ^= 1) {
        const int ktn = kt + NSPLIT;
        float4 nka, nkb, nva, nvb;
        const bool has_next = ktn < ntB;
        if (has_next) {
            const float4* ks = (const float4*)(kbase + (size_t)ktn * 64 * D_);
            const float4* vs = (const float4*)(vbase + (size_t)ktn * 64 * D_);
            nka = ks[tid]; nkb = ks[tid + 128];
            nva = vs[tid]; nvb = vs[tid + 128];
        }
        __syncthreads();   // buf fully written; prior compute on buf^1 done

        const ulonglong2* Ks2 = (const ulonglong2*)Ks[buf];
        const ulonglong2* Vs2 = (const ulonglong2*)Vs[buf];
        const int jthrA = qa - kt * 64;
        const int jthrB = qb - kt * 64;
        if (kt < ntA) {
            if (kt < 2 * p) {
                attn_inner<true, false>(Ks2, Vs2, qA, qB, oA, oB, lA, lB, jthrA, jthrB);
            } else if (kt == 2 * p) {
                // jthrA = tid: warps 2-3 fully unmasked (tid >= 64 > 63)
                if (wid >= 2)
                    attn_inner<true, false>(Ks2, Vs2, qA, qB, oA, oB, lA, lB, jthrA, jthrB);
                else
                    attn_inner<true, true >(Ks2, Vs2, qA, qB, oA, oB, lA, lB, jthrA, jthrB);
            } else { // kt == 2p+1: jthrA = tid-64: warps 0-1 A fully dead
                if (wid < 2)
                    attn_inner<false, false>(Ks2, Vs2, qA, qB, oA, oB, lA, lB, jthrA, jthrB);
                else
                    attn_inner<true,  true >(Ks2, Vs2, qA, qB, oA, oB, lA, lB, jthrA, jthrB);
            }
        } else {
            if (kt < ntB - 2) {
                attn_inner<false, false>(Ks2, Vs2, qA, qB, oA, oB, lA, lB, jthrA, jthrB);
            } else if (kt == ntB - 2) {
                // jthrB = tid: warps 2-3 fully unmasked
                if (wid >= 2)
                    attn_inner<false, false>(Ks2, Vs2, qA, qB, oA, oB, lA, lB, jthrA, jthrB);
                else
                    attn_inner<false, true >(Ks2, Vs2, qA, qB, oA, oB, lA, lB, jthrA, jthrB);
            } else { // kt == ntB-1: jthrB = tid-64: warps 0-1 fully masked -> skip
                if (wid >= 2)
                    attn_inner<false, true >(Ks2, Vs2, qA, qB, oA, oB, lA, lB, jthrA, jthrB);
            }
        }

        if (has_next) {
            const int nb = buf ^ 1;
            ((float4*)Ks[nb])[tid]       = nka;
            ((float4*)Ks[nb])[tid + 128] = nkb;
            ((float4*)Vs[nb])[tid]       = nva;
            ((float4*)Vs[nb])[tid + 128] = nvb;
        }
    }

    // ---- write partials (merge kernel combines residues) --------------------
    const size_t ia = (size_t)half * PART_Q + (size_t)bh * S_ + qa;
    const size_t ib = (size_t)half * PART_Q + (size_t)bh * S_ + qb;
    float* poa = g_po + ia * 16;
    float* pob = g_po + ib * 16;
#pragma unroll
    for (int i = 0; i < 8; i++) {
        *(u64*)&poa[2 * i] = oA[i];
        *(u64*)&pob[2 * i] = oB[i];
    }
    g_pl[ia] = lA;
    g_pl[ib] = lB;
}

// Merge the NSPLIT residues: out = sum(o)/sum(l), scattered into g_ao.
// One thread per (query, 4-float chunk) for parallelism.
__global__ __launch_bounds__(256) void merge_attn_kernel()
{
    int idx = blockIdx.x * blockDim.x + threadIdx.x;  // PART_Q * 4
    if (idx >= PART_Q * 4) return;
    const int q = idx >> 2, c = idx & 3;
    float l = g_pl[q] + g_pl[PART_Q + q] + g_pl[2 * PART_Q + q] + g_pl[3 * PART_Q + q];
    const float inv = 1.0f / l;
    float4 a0 = *(const float4*)(g_po + ((size_t)q * 16) + c * 4);
    float4 a1 = *(const float4*)(g_po + (((size_t)PART_Q + q) * 16) + c * 4);
    float4 a2 = *(const float4*)(g_po + (((size_t)2 * PART_Q + q) * 16) + c * 4);
    float4 a3 = *(const float4*)(g_po + (((size_t)3 * PART_Q + q) * 16) + c * 4);
    float4 r;
    r.x = (a0.x + a1.x + a2.x + a3.x) * inv;
    r.y = (a0.y + a1.y + a2.y + a3.y) * inv;
    r.z = (a0.z + a1.z + a2.z + a3.z) * inv;
    r.w = (a0.w + a1.w + a2.w + a3.w) * inv;
    const int bh = q >> 11, s = q & 2047;
    const int b = bh / NH_, h = bh % NH_;
    *(float4*)(g_ao + ((size_t)(b * S_ + s)) * H_ + h * D_ + c * 4) = r;
}

// =============================================================================
// Kernel 4: output projection, split-K x3 -> partials; kernel 5 reduces.
// =============================================================================
__global__ __launch_bounds__(256) void gemm_out_kernel(
    const float* __restrict__ W)
{
    __shared__ __align__(16) float Xs[2][64][PAD_];
    __shared__ __align__(16) float Ws[2][96][PAD_];

    const int m0 = blockIdx.x * 64;
    const int n0 = blockIdx.y * 96;
    const int ks = blockIdx.z;
    const int tid = threadIdx.x;

    u64 acc[4][6];
#pragma unroll
    for (int i = 0; i < 4; i++)
#pragma unroll
        for (int j = 0; j < 6; j++) acc[i][j] = 0ULL;

    gemm_core<3>(g_ao, W, m0, n0, ks * 96, tid, Xs, Ws, acc);

    float* P = g_part + (size_t)ks * M_TOT * H_;
    const int tr4 = (tid >> 4) * 4, tc = tid & 15;
#pragma unroll
    for (int i = 0; i < 4; i++) {
        size_t m = m0 + tr4 + i;
#pragma unroll
        for (int j = 0; j < 6; j++) {
            float lo, hi; unpk2(acc[i][j], lo, hi);
            P[m * 288 + n0 + tc + 16 * j] = lo + hi;
        }
    }
}

__global__ __launch_bounds__(256) void reduce_out_kernel(float* __restrict__ Y)
{
    const int N4 = M_TOT * H_ / 4;
    int i = blockIdx.x * blockDim.x + threadIdx.x;
    if (i >= N4) return;
    const float4* P = (const float4*)g_part;
    float4 a = P[i], b = P[i + N4], c = P[i + 2 * N4];
    float4 r;
    r.x = a.x + b.x + c.x;
    r.y = a.y + b.y + c.y;
    r.z = a.z + b.z + c.z;
    r.w = a.w + b.w + c.w;
    ((float4*)Y)[i] = r;
}

// =============================================================================
extern "C" void kernel_launch(void* const* d_in, const int* in_sizes, int n_in,
                              void* d_out, int out_size)
{
    const float* hs = (const float*)d_in[0];
    const float* Wq = (const float*)d_in[1];
    const float* Wk = (const float*)d_in[2];
    const float* Wv = (const float*)d_in[3];
    const float* Wo = (const float*)d_in[4];
    float* out = (float*)d_out;

    gemm_qkv_kernel<<<dim3(64, 9), 256>>>(hs, Wq, Wk, Wv);

    const int rope_total = 2 * B_ * NH_ * S_ * 8;
    rope_kernel<<<(rope_total + 255) / 256, 256>>>();

    attn_kernel<<<dim3(8, 36, NSPLIT), 128>>>();
    merge_attn_kernel<<<(PART_Q * 4 + 255) / 256, 256>>>();

    gemm_out_kernel<<<dim3(64, 3, 3), 256>>>(Wo);
    reduce_out_kernel<<<(M_TOT * H_ / 4 + 255) / 256, 256>>>(out);
}

// round 14
// speedup vs baseline: 1.6259x; 1.6259x over previous
#include <cuda_runtime.h>
#include <math.h>

// Problem constants (fixed by reference)
#define B_    2
#define S_    2048
#define H_    288
#define NH_   18
#define D_    16
#define M_TOT (B_ * S_)                  // 4096
#define QKV_ELEMS (B_ * NH_ * S_ * D_)   // 1,179,648
#define PART_Q (36 * 2048)               // queries across all (b,h)
#define NSPLIT 4                         // attention split-K ways (4 is load-bearing)

typedef unsigned long long u64;

// ---------------- scratch (device globals; no allocation allowed) -----------
__device__ float g_q[QKV_ELEMS];
__device__ float g_k[QKV_ELEMS];
__device__ float g_v[QKV_ELEMS];
__device__ float g_ao[M_TOT * H_];
__device__ float g_part[3 * M_TOT * H_];        // split-K partials for out proj
__device__ float g_po[NSPLIT * PART_Q * 16];    // attention split-K o partials
__device__ float g_pl[NSPLIT * PART_Q];         // attention split-K l partials

// exact 10000^(-d/8) = 10^(-d/2) table for RoPE
__constant__ float c_inv[8] = {
    1.0f, 0.31622776601683794f, 0.1f, 0.031622776601683794f,
    0.01f, 0.0031622776601683794f, 0.001f, 0.00031622776601683794f
};

// 0.25 * log2(e): folds 1/sqrt(D) and the exp->exp2 conversion into q
#define QSCALE 0.36067376022224085f

// ---------------- f32x2 helpers (Blackwell packed fp32) ---------------------
__device__ __forceinline__ u64 pk2(float lo, float hi) {
    u64 r;
    asm("mov.b64 %0, {%1, %2};" : "=l"(r) : "f"(lo), "f"(hi));
    return r;
}
__device__ __forceinline__ void unpk2(u64 a, float& lo, float& hi) {
    asm("mov.b64 {%0, %1}, %2;" : "=f"(lo), "=f"(hi) : "l"(a));
}
__device__ __forceinline__ u64 fma2(u64 a, u64 b, u64 c) {
    u64 d;
    asm("fma.rn.f32x2 %0, %1, %2, %3;" : "=l"(d) : "l"(a), "l"(b), "l"(c));
    return d;
}
__device__ __forceinline__ u64 mul2(u64 a, u64 b) {
    u64 d;
    asm("mul.rn.f32x2 %0, %1, %2;" : "=l"(d) : "l"(a), "l"(b));
    return d;
}
__device__ __forceinline__ u64 add2(u64 a, u64 b) {
    u64 d;
    asm("add.rn.f32x2 %0, %1, %2;" : "=l"(d) : "l"(a), "l"(b));
    return d;
}
// Guaranteed single MUFU.EX2.
__device__ __forceinline__ float ex2(float x) {
    float y;
    asm("ex2.approx.ftz.f32 %0, %1;" : "=f"(y) : "f"(x));
    return y;
}

// =============================================================================
// k-packed GEMM core: 64(m) x 96(n) block tile, 256 threads, 4m x 6n/thread.
// PAD_=34: stride-34 u64 reads map to bank 2*tc -> conflict-free (R10-proven).
// =============================================================================
#define PAD_ 34

template<int NCHUNKS>
__device__ __forceinline__ void gemm_core(
    const float* __restrict__ X, const float* __restrict__ W,
    int m0, int n0, int kbase, int tid,
    float (&Xs)[2][64][PAD_], float (&Ws)[2][96][PAD_],
    u64 (&acc)[4][6])
{
    const int tr4 = (tid >> 4) * 4;
    const int tc  = tid & 15;

    const int lr = tid >> 3;
    const int lq = (tid & 7) << 2;

    const float* Xp0 = X + (size_t)(m0 + lr)      * 288 + kbase + lq;
    const float* Xp1 = X + (size_t)(m0 + lr + 32) * 288 + kbase + lq;
    const float* Wp0 = W + (size_t)(n0 + lr)      * 288 + kbase + lq;
    const float* Wp1 = W + (size_t)(n0 + lr + 32) * 288 + kbase + lq;
    const float* Wp2 = W + (size_t)(n0 + lr + 64) * 288 + kbase + lq;

    {
        float4 a = *(const float4*)Xp0;
        float4 b = *(const float4*)Xp1;
        float4 c = *(const float4*)Wp0;
        float4 d = *(const float4*)Wp1;
        float4 e = *(const float4*)Wp2;
        *(float2*)&Xs[0][lr     ][lq    ] = make_float2(a.x, a.y);
        *(float2*)&Xs[0][lr     ][lq + 2] = make_float2(a.z, a.w);
        *(float2*)&Xs[0][lr + 32][lq    ] = make_float2(b.x, b.y);
        *(float2*)&Xs[0][lr + 32][lq + 2] = make_float2(b.z, b.w);
        *(float2*)&Ws[0][lr     ][lq    ] = make_float2(c.x, c.y);
        *(float2*)&Ws[0][lr     ][lq + 2] = make_float2(c.z, c.w);
        *(float2*)&Ws[0][lr + 32][lq    ] = make_float2(d.x, d.y);
        *(float2*)&Ws[0][lr + 32][lq + 2] = make_float2(d.z, d.w);
        *(float2*)&Ws[0][lr + 64][lq    ] = make_float2(e.x, e.y);
        *(float2*)&Ws[0][lr + 64][lq + 2] = make_float2(e.z, e.w);
    }

    for (int it = 0; it < NCHUNKS; it++) {
        const int buf = it & 1;
        float4 a, b, c, d, e;
        if (it < NCHUNKS - 1) {
            const int ko = (it + 1) * 32;
            a = *(const float4*)(Xp0 + ko);
            b = *(const float4*)(Xp1 + ko);
            c = *(const float4*)(Wp0 + ko);
            d = *(const float4*)(Wp1 + ko);
            e = *(const float4*)(Wp2 + ko);
        }
        __syncthreads();
#pragma unroll
        for (int kk = 0; kk < 16; kk++) {
            u64 x[4], w[6];
#pragma unroll
            for (int i = 0; i < 4; i++)
                x[i] = *(const u64*)&Xs[buf][tr4 + i][2 * kk];
#pragma unroll
            for (int j = 0; j < 6; j++)
                w[j] = *(const u64*)&Ws[buf][tc + 16 * j][2 * kk];
#pragma unroll
            for (int i = 0; i < 4; i++)
#pragma unroll
                for (int j = 0; j < 6; j++)
                    acc[i][j] = fma2(x[i], w[j], acc[i][j]);
        }
        if (it < NCHUNKS - 1) {
            const int nb = buf ^ 1;
            *(float2*)&Xs[nb][lr     ][lq    ] = make_float2(a.x, a.y);
            *(float2*)&Xs[nb][lr     ][lq + 2] = make_float2(a.z, a.w);
            *(float2*)&Xs[nb][lr + 32][lq    ] = make_float2(b.x, b.y);
            *(float2*)&Xs[nb][lr + 32][lq + 2] = make_float2(b.z, b.w);
            *(float2*)&Ws[nb][lr     ][lq    ] = make_float2(c.x, c.y);
            *(float2*)&Ws[nb][lr     ][lq + 2] = make_float2(c.z, c.w);
            *(float2*)&Ws[nb][lr + 32][lq    ] = make_float2(d.x, d.y);
            *(float2*)&Ws[nb][lr + 32][lq + 2] = make_float2(d.z, d.w);
            *(float2*)&Ws[nb][lr + 64][lq    ] = make_float2(e.x, e.y);
            *(float2*)&Ws[nb][lr + 64][lq + 2] = make_float2(e.z, e.w);
        }
    }
}

// =============================================================================
// Kernel 1: fused QKV projection with scatter epilogue into [b,h,s,d].
// =============================================================================
__global__ __launch_bounds__(256) void gemm_qkv_kernel(
    const float* __restrict__ X,
    const float* __restrict__ Wq,
    const float* __restrict__ Wk,
    const float* __restrict__ Wv)
{
    __shared__ __align__(16) float Xs[2][64][PAD_];
    __shared__ __align__(16) float Ws[2][96][PAD_];

    const int m0 = blockIdx.x * 64;
    const int cb = blockIdx.y;
    const float* __restrict__ W = (cb < 3) ? Wq : (cb < 6 ? Wk : Wv);
    float* dst = (cb < 3) ? g_q : (cb < 6 ? g_k : g_v);
    const int n0 = (cb % 3) * 96;
    const int tid = threadIdx.x;

    u64 acc[4][6];
#pragma unroll
    for (int i = 0; i < 4; i++)
#pragma unroll
        for (int j = 0; j < 6; j++) acc[i][j] = 0ULL;

    gemm_core<9>(X, W, m0, n0, 0, tid, Xs, Ws, acc);

    const int tr4 = (tid >> 4) * 4, tc = tid & 15;
#pragma unroll
    for (int i = 0; i < 4; i++) {
        int m = m0 + tr4 + i;
        int b = m >> 11, s = m & 2047;
#pragma unroll
        for (int j = 0; j < 6; j++) {
            float lo, hi; unpk2(acc[i][j], lo, hi);
            int c = n0 + tc + 16 * j;
            int h = c >> 4, d = c & 15;
            dst[(((size_t)(b * NH_ + h)) * S_ + s) * D_ + d] = lo + hi;
        }
    }
}

// =============================================================================
// Kernel 2: RoPE in-place; folds (1/sqrt(D)) * log2(e) into q.
// =============================================================================
__global__ void rope_kernel()
{
    int idx = blockIdx.x * blockDim.x + threadIdx.x;
    const int total = 2 * B_ * NH_ * S_ * 8;
    if (idx >= total) return;
    int d = idx & 7;
    int s = (idx >> 3) & (S_ - 1);
    int v = idx >> 14;
    bool isq = v < 36;
    float* base = (isq ? g_q : g_k) + (((size_t)(v % 36)) * S_ + s) * D_;
    float f = (float)s * c_inv[d];
    float sn, cs;
    sincosf(f, &sn, &cs);
    float scale = isq ? QSCALE : 1.0f;
    float x0 = base[d];
    float x1 = base[d + 8];
    base[d]     = (x0 * cs - x1 * sn) * scale;
    base[d + 8] = (x1 * cs + x0 * sn) * scale;
}

// =============================================================================
// Kernel 3: causal attention, split-K x4, double-buffered K/V,
// WARP-uniform mask specialization:
//   tile kt==2p   : warps 0-1 masked-A, warps 2-3 provably-unmasked A
//   tile kt==2p+1 : warps 0-1 A fully dead -> B-only; warps 2-3 masked-A
//   tile ntB-2    : warps 0-1 masked-B, warps 2-3 unmasked
//   tile ntB-1    : warps 0-1 SKIP ENTIRELY; warps 2-3 masked-B
// =============================================================================
template<bool BOTH, bool MASK>
__device__ __forceinline__ void attn_inner(
    const ulonglong2* __restrict__ Ks2, const ulonglong2* __restrict__ Vs2,
    const u64 (&qA)[8], const u64 (&qB)[8],
    u64 (&oA)[8], u64 (&oB)[8],
    float& lA, float& lB, int jthrA, int jthrB)
{
#pragma unroll 2
    for (int j = 0; j < 64; j++) {
        ulonglong2 k0 = Ks2[j * 4 + 0];
        ulonglong2 k1 = Ks2[j * 4 + 1];
        ulonglong2 k2 = Ks2[j * 4 + 2];
        ulonglong2 k3 = Ks2[j * 4 + 3];

        u64 b0 = mul2(qB[0], k0.x), b1 = mul2(qB[1], k0.y);
        b0 = fma2(qB[2], k1.x, b0); b1 = fma2(qB[3], k1.y, b1);
        b0 = fma2(qB[4], k2.x, b0); b1 = fma2(qB[5], k2.y, b1);
        b0 = fma2(qB[6], k3.x, b0); b1 = fma2(qB[7], k3.y, b1);
        u64 bs = add2(b0, b1);
        float blo, bhi; unpk2(bs, blo, bhi);
        float sB = blo + bhi;
        float pB;
        if (!BOTH && MASK) pB = (j <= jthrB) ? ex2(sB) : 0.0f;
        else               pB = ex2(sB);
        lB += pB;

        float pA = 0.0f;
        if (BOTH) {
            u64 a0 = mul2(qA[0], k0.x), a1 = mul2(qA[1], k0.y);
            a0 = fma2(qA[2], k1.x, a0); a1 = fma2(qA[3], k1.y, a1);
            a0 = fma2(qA[4], k2.x, a0); a1 = fma2(qA[5], k2.y, a1);
            a0 = fma2(qA[6], k3.x, a0); a1 = fma2(qA[7], k3.y, a1);
            u64 as = add2(a0, a1);
            float alo, ahi; unpk2(as, alo, ahi);
            float sA = alo + ahi;
            if (MASK) pA = (j <= jthrA) ? ex2(sA) : 0.0f;
            else      pA = ex2(sA);
            lA += pA;
        }

        ulonglong2 v0 = Vs2[j * 4 + 0];
        ulonglong2 v1 = Vs2[j * 4 + 1];
        ulonglong2 v2 = Vs2[j * 4 + 2];
        ulonglong2 v3 = Vs2[j * 4 + 3];

        u64 pB2 = pk2(pB, pB);
        oB[0] = fma2(pB2, v0.x, oB[0]); oB[1] = fma2(pB2, v0.y, oB[1]);
        oB[2] = fma2(pB2, v1.x, oB[2]); oB[3] = fma2(pB2, v1.y, oB[3]);
        oB[4] = fma2(pB2, v2.x, oB[4]); oB[5] = fma2(pB2, v2.y, oB[5]);
        oB[6] = fma2(pB2, v3.x, oB[6]); oB[7] = fma2(pB2, v3.y, oB[7]);
        if (BOTH) {
            u64 pA2 = pk2(pA, pA);
            oA[0] = fma2(pA2, v0.x, oA[0]); oA[1] = fma2(pA2, v0.y, oA[1]);
            oA[2] = fma2(pA2, v1.x, oA[2]); oA[3] = fma2(pA2, v1.y, oA[3]);
            oA[4] = fma2(pA2, v2.x, oA[4]); oA[5] = fma2(pA2, v2.y, oA[5]);
            oA[6] = fma2(pA2, v3.x, oA[6]); oA[7] = fma2(pA2, v3.y, oA[7]);
        }
    }
}

__global__ __launch_bounds__(128) void attn_kernel()
{
    __shared__ __align__(16) float Ks[2][64 * 16];
    __shared__ __align__(16) float Vs[2][64 * 16];

    const int bh   = blockIdx.y;                     // 0..35
    const int p    = blockIdx.x;                     // 0..7 (pair index)
    const int half = blockIdx.z;                     // 0..NSPLIT-1 (tile residue)
    const int tid  = threadIdx.x;
    const int wid  = tid >> 5;                       // warp 0..3
    const int qa = p * 128 + tid;                    // short query
    const int qb = (15 - p) * 128 + tid;             // long query
    const int ntA = 2 * p + 2;
    const int ntB = 32 - 2 * p;

    const float* qpa = g_q + ((size_t)bh * S_ + qa) * D_;
    const float* qpb = g_q + ((size_t)bh * S_ + qb) * D_;
    u64 qA[8], qB[8];
#pragma unroll
    for (int c = 0; c < 8; c++) {
        qA[c] = *(const u64*)(qpa + 2 * c);          // pre-scaled in rope
        qB[c] = *(const u64*)(qpb + 2 * c);
    }
    u64 oA[8], oB[8];
#pragma unroll
    for (int i = 0; i < 8; i++) { oA[i] = 0ULL; oB[i] = 0ULL; }
    float lA = 0.0f, lB = 0.0f;

    const float* kbase = g_k + (size_t)bh * S_ * D_;
    const float* vbase = g_v + (size_t)bh * S_ * D_;

    // ---- prologue: first tile into buffer 0 ---------------------------------
    {
        const float4* ks = (const float4*)(kbase + (size_t)half * 64 * D_);
        const float4* vs = (const float4*)(vbase + (size_t)half * 64 * D_);
        float4 ka = ks[tid], kb = ks[tid + 128];
        float4 va = vs[tid], vb = vs[tid + 128];
        ((float4*)Ks[0])[tid]       = ka;
        ((float4*)Ks[0])[tid + 128] = kb;
        ((float4*)Vs[0])[tid]       = va;
        ((float4*)Vs[0])[tid + 128] = vb;
    }

    int buf = 0;
    for (int kt = half; kt < ntB; kt += NSPLIT, buf ^= 1) {
        const int ktn = kt + NSPLIT;
        float4 nka, nkb, nva, nvb;
        const bool has_next = ktn < ntB;
        if (has_next) {
            const float4* ks = (const float4*)(kbase + (size_t)ktn * 64 * D_);
            const float4* vs = (const float4*)(vbase + (size_t)ktn * 64 * D_);
            nka = ks[tid]; nkb = ks[tid + 128];
            nva = vs[tid]; nvb = vs[tid + 128];
        }
        __syncthreads();   // buf fully written; prior compute on buf^1 done

        const ulonglong2* Ks2 = (const ulonglong2*)Ks[buf];
        const ulonglong2* Vs2 = (const ulonglong2*)Vs[buf];
        const int jthrA = qa - kt * 64;
        const int jthrB = qb - kt * 64;
        if (kt < ntA) {
            if (kt < 2 * p) {
                attn_inner<true, false>(Ks2, Vs2, qA, qB, oA, oB, lA, lB, jthrA, jthrB);
            } else if (kt == 2 * p) {
                // jthrA = tid: warps 2-3 fully unmasked (tid >= 64 > 63)
                if (wid >= 2)
                    attn_inner<true, false>(Ks2, Vs2, qA, qB, oA, oB, lA, lB, jthrA, jthrB);
                else
                    attn_inner<true, true >(Ks2, Vs2, qA, qB, oA, oB, lA, lB, jthrA, jthrB);
            } else { // kt == 2p+1: jthrA = tid-64: warps 0-1 A fully dead
                if (wid < 2)
                    attn_inner<false, false>(Ks2, Vs2, qA, qB, oA, oB, lA, lB, jthrA, jthrB);
                else
                    attn_inner<true,  true >(Ks2, Vs2, qA, qB, oA, oB, lA, lB, jthrA, jthrB);
            }
        } else {
            if (kt < ntB - 2) {
                attn_inner<false, false>(Ks2, Vs2, qA, qB, oA, oB, lA, lB, jthrA, jthrB);
            } else if (kt == ntB - 2) {
                // jthrB = tid: warps 2-3 fully unmasked
                if (wid >= 2)
                    attn_inner<false, false>(Ks2, Vs2, qA, qB, oA, oB, lA, lB, jthrA, jthrB);
                else
                    attn_inner<false, true >(Ks2, Vs2, qA, qB, oA, oB, lA, lB, jthrA, jthrB);
            } else { // kt == ntB-1: jthrB = tid-64: warps 0-1 fully masked -> skip
                if (wid >= 2)
                    attn_inner<false, true >(Ks2, Vs2, qA, qB, oA, oB, lA, lB, jthrA, jthrB);
            }
        }

        if (has_next) {
            const int nb = buf ^ 1;
            ((float4*)Ks[nb])[tid]       = nka;
            ((float4*)Ks[nb])[tid + 128] = nkb;
            ((float4*)Vs[nb])[tid]       = nva;
            ((float4*)Vs[nb])[tid + 128] = nvb;
        }
    }

    // ---- write partials (merge kernel combines residues) --------------------
    const size_t ia = (size_t)half * PART_Q + (size_t)bh * S_ + qa;
    const size_t ib = (size_t)half * PART_Q + (size_t)bh * S_ + qb;
    float* poa = g_po + ia * 16;
    float* pob = g_po + ib * 16;
#pragma unroll
    for (int i = 0; i < 8; i++) {
        *(u64*)&poa[2 * i] = oA[i];
        *(u64*)&pob[2 * i] = oB[i];
    }
    g_pl[ia] = lA;
    g_pl[ib] = lB;
}

// Merge the NSPLIT residues: out = sum(o)/sum(l), scattered into g_ao.
// One thread per (query, 4-float chunk) for parallelism.
__global__ __launch_bounds__(256) void merge_attn_kernel()
{
    int idx = blockIdx.x * blockDim.x + threadIdx.x;  // PART_Q * 4
    if (idx >= PART_Q * 4) return;
    const int q = idx >> 2, c = idx & 3;
    float l = g_pl[q] + g_pl[PART_Q + q] + g_pl[2 * PART_Q + q] + g_pl[3 * PART_Q + q];
    const float inv = 1.0f / l;
    float4 a0 = *(const float4*)(g_po + ((size_t)q * 16) + c * 4);
    float4 a1 = *(const float4*)(g_po + (((size_t)PART_Q + q) * 16) + c * 4);
    float4 a2 = *(const float4*)(g_po + (((size_t)2 * PART_Q + q) * 16) + c * 4);
    float4 a3 = *(const float4*)(g_po + (((size_t)3 * PART_Q + q) * 16) + c * 4);
    float4 r;
    r.x = (a0.x + a1.x + a2.x + a3.x) * inv;
    r.y = (a0.y + a1.y + a2.y + a3.y) * inv;
    r.z = (a0.z + a1.z + a2.z + a3.z) * inv;
    r.w = (a0.w + a1.w + a2.w + a3.w) * inv;
    const int bh = q >> 11, s = q & 2047;
    const int b = bh / NH_, h = bh % NH_;
    *(float4*)(g_ao + ((size_t)(b * S_ + s)) * H_ + h * D_ + c * 4) = r;
}

// =============================================================================
// Kernel 4: output projection, split-K x3 -> partials; kernel 5 reduces.
// =============================================================================
__global__ __launch_bounds__(256) void gemm_out_kernel(
    const float* __restrict__ W)
{
    __shared__ __align__(16) float Xs[2][64][PAD_];
    __shared__ __align__(16) float Ws[2][96][PAD_];

    const int m0 = blockIdx.x * 64;
    const int n0 = blockIdx.y * 96;
    const int ks = blockIdx.z;
    const int tid = threadIdx.x;

    u64 acc[4][6];
#pragma unroll
    for (int i = 0; i < 4; i++)
#pragma unroll
        for (int j = 0; j < 6; j++) acc[i][j] = 0ULL;

    gemm_core<3>(g_ao, W, m0, n0, ks * 96, tid, Xs, Ws, acc);

    float* P = g_part + (size_t)ks * M_TOT * H_;
    const int tr4 = (tid >> 4) * 4, tc = tid & 15;
#pragma unroll
    for (int i = 0; i < 4; i++) {
        size_t m = m0 + tr4 + i;
#pragma unroll
        for (int j = 0; j < 6; j++) {
            float lo, hi; unpk2(acc[i][j], lo, hi);
            P[m * 288 + n0 + tc + 16 * j] = lo + hi;
        }
    }
}

__global__ __launch_bounds__(256) void reduce_out_kernel(float* __restrict__ Y)
{
    const int N4 = M_TOT * H_ / 4;
    int i = blockIdx.x * blockDim.x + threadIdx.x;
    if (i >= N4) return;
    const float4* P = (const float4*)g_part;
    float4 a = P[i], b = P[i + N4], c = P[i + 2 * N4];
    float4 r;
    r.x = a.x + b.x + c.x;
    r.y = a.y + b.y + c.y;
    r.z = a.z + b.z + c.z;
    r.w = a.w + b.w + c.w;
    ((float4*)Y)[i] = r;
}

// =============================================================================
extern "C" void kernel_launch(void* const* d_in, const int* in_sizes, int n_in,
                              void* d_out, int out_size)
{
    const float* hs = (const float*)d_in[0];
    const float* Wq = (const float*)d_in[1];
    const float* Wk = (const float*)d_in[2];
    const float* Wv = (const float*)d_in[3];
    const float* Wo = (const float*)d_in[4];
    float* out = (float*)d_out;

    gemm_qkv_kernel<<<dim3(64, 9), 256>>>(hs, Wq, Wk, Wv);

    const int rope_total = 2 * B_ * NH_ * S_ * 8;
    rope_kernel<<<(rope_total + 255) / 256, 256>>>();

    attn_kernel<<<dim3(8, 36, NSPLIT), 128>>>();
    merge_attn_kernel<<<(PART_Q * 4 + 255) / 256, 256>>>();

    gemm_out_kernel<<<dim3(64, 3, 3), 256>>>(Wo);
    reduce_out_kernel<<<(M_TOT * H_ / 4 + 255) / 256, 256>>>(out);
}

// round 15
// speedup vs baseline: 1.6392x; 1.0082x over previous
#include <cuda_runtime.h>
#include <math.h>

// Problem constants (fixed by reference)
#define B_    2
#define S_    2048
#define H_    288
#define NH_   18
#define D_    16
#define M_TOT (B_ * S_)                  // 4096
#define QKV_ELEMS (B_ * NH_ * S_ * D_)   // 1,179,648
#define PART_Q (36 * 2048)               // queries across all (b,h)
#define NSPLIT 4                         // attention split-K ways (4 is load-bearing)

typedef unsigned long long u64;

// ---------------- scratch (device globals; no allocation allowed) -----------
__device__ float g_q[QKV_ELEMS];
__device__ float g_k[QKV_ELEMS];
__device__ float g_v[QKV_ELEMS];
__device__ float g_ao[M_TOT * H_];
__device__ float g_part[3 * M_TOT * H_];        // split-K partials for out proj
__device__ float g_po[NSPLIT * PART_Q * 16];    // attention split-K o partials
__device__ float g_pl[NSPLIT * PART_Q];         // attention split-K l partials

// exact 10000^(-d/8) = 10^(-d/2) table for RoPE
__constant__ float c_inv[8] = {
    1.0f, 0.31622776601683794f, 0.1f, 0.031622776601683794f,
    0.01f, 0.0031622776601683794f, 0.001f, 0.00031622776601683794f
};

// 0.25 * log2(e): folds 1/sqrt(D) and the exp->exp2 conversion into q
#define QSCALE 0.36067376022224085f

// ---------------- f32x2 helpers (Blackwell packed fp32) ---------------------
__device__ __forceinline__ u64 pk2(float lo, float hi) {
    u64 r;
    asm("mov.b64 %0, {%1, %2};" : "=l"(r) : "f"(lo), "f"(hi));
    return r;
}
__device__ __forceinline__ void unpk2(u64 a, float& lo, float& hi) {
    asm("mov.b64 {%0, %1}, %2;" : "=f"(lo), "=f"(hi) : "l"(a));
}
__device__ __forceinline__ u64 fma2(u64 a, u64 b, u64 c) {
    u64 d;
    asm("fma.rn.f32x2 %0, %1, %2, %3;" : "=l"(d) : "l"(a), "l"(b), "l"(c));
    return d;
}
__device__ __forceinline__ u64 mul2(u64 a, u64 b) {
    u64 d;
    asm("mul.rn.f32x2 %0, %1, %2;" : "=l"(d) : "l"(a), "l"(b));
    return d;
}
__device__ __forceinline__ u64 add2(u64 a, u64 b) {
    u64 d;
    asm("add.rn.f32x2 %0, %1, %2;" : "=l"(d) : "l"(a), "l"(b));
    return d;
}
// Guaranteed single MUFU.EX2.
__device__ __forceinline__ float ex2(float x) {
    float y;
    asm("ex2.approx.ftz.f32 %0, %1;" : "=f"(y) : "f"(x));
    return y;
}

// =============================================================================
// k-packed GEMM core: 64(m) x 96(n) block tile, 256 threads, 4m x 6n/thread.
// PAD_=34: stride-34 u64 reads map to bank 2*tc -> conflict-free (R10-proven).
// =============================================================================
#define PAD_ 34

template<int NCHUNKS>
__device__ __forceinline__ void gemm_core(
    const float* __restrict__ X, const float* __restrict__ W,
    int m0, int n0, int kbase, int tid,
    float (&Xs)[2][64][PAD_], float (&Ws)[2][96][PAD_],
    u64 (&acc)[4][6])
{
    const int tr4 = (tid >> 4) * 4;
    const int tc  = tid & 15;

    const int lr = tid >> 3;
    const int lq = (tid & 7) << 2;

    const float* Xp0 = X + (size_t)(m0 + lr)      * 288 + kbase + lq;
    const float* Xp1 = X + (size_t)(m0 + lr + 32) * 288 + kbase + lq;
    const float* Wp0 = W + (size_t)(n0 + lr)      * 288 + kbase + lq;
    const float* Wp1 = W + (size_t)(n0 + lr + 32) * 288 + kbase + lq;
    const float* Wp2 = W + (size_t)(n0 + lr + 64) * 288 + kbase + lq;

    {
        float4 a = *(const float4*)Xp0;
        float4 b = *(const float4*)Xp1;
        float4 c = *(const float4*)Wp0;
        float4 d = *(const float4*)Wp1;
        float4 e = *(const float4*)Wp2;
        *(float2*)&Xs[0][lr     ][lq    ] = make_float2(a.x, a.y);
        *(float2*)&Xs[0][lr     ][lq + 2] = make_float2(a.z, a.w);
        *(float2*)&Xs[0][lr + 32][lq    ] = make_float2(b.x, b.y);
        *(float2*)&Xs[0][lr + 32][lq + 2] = make_float2(b.z, b.w);
        *(float2*)&Ws[0][lr     ][lq    ] = make_float2(c.x, c.y);
        *(float2*)&Ws[0][lr     ][lq + 2] = make_float2(c.z, c.w);
        *(float2*)&Ws[0][lr + 32][lq    ] = make_float2(d.x, d.y);
        *(float2*)&Ws[0][lr + 32][lq + 2] = make_float2(d.z, d.w);
        *(float2*)&Ws[0][lr + 64][lq    ] = make_float2(e.x, e.y);
        *(float2*)&Ws[0][lr + 64][lq + 2] = make_float2(e.z, e.w);
    }

    for (int it = 0; it < NCHUNKS; it++) {
        const int buf = it & 1;
        float4 a, b, c, d, e;
        if (it < NCHUNKS - 1) {
            const int ko = (it + 1) * 32;
            a = *(const float4*)(Xp0 + ko);
            b = *(const float4*)(Xp1 + ko);
            c = *(const float4*)(Wp0 + ko);
            d = *(const float4*)(Wp1 + ko);
            e = *(const float4*)(Wp2 + ko);
        }
        __syncthreads();
#pragma unroll
        for (int kk = 0; kk < 16; kk++) {
            u64 x[4], w[6];
#pragma unroll
            for (int i = 0; i < 4; i++)
                x[i] = *(const u64*)&Xs[buf][tr4 + i][2 * kk];
#pragma unroll
            for (int j = 0; j < 6; j++)
                w[j] = *(const u64*)&Ws[buf][tc + 16 * j][2 * kk];
#pragma unroll
            for (int i = 0; i < 4; i++)
#pragma unroll
                for (int j = 0; j < 6; j++)
                    acc[i][j] = fma2(x[i], w[j], acc[i][j]);
        }
        if (it < NCHUNKS - 1) {
            const int nb = buf ^ 1;
            *(float2*)&Xs[nb][lr     ][lq    ] = make_float2(a.x, a.y);
            *(float2*)&Xs[nb][lr     ][lq + 2] = make_float2(a.z, a.w);
            *(float2*)&Xs[nb][lr + 32][lq    ] = make_float2(b.x, b.y);
            *(float2*)&Xs[nb][lr + 32][lq + 2] = make_float2(b.z, b.w);
            *(float2*)&Ws[nb][lr     ][lq    ] = make_float2(c.x, c.y);
            *(float2*)&Ws[nb][lr     ][lq + 2] = make_float2(c.z, c.w);
            *(float2*)&Ws[nb][lr + 32][lq    ] = make_float2(d.x, d.y);
            *(float2*)&Ws[nb][lr + 32][lq + 2] = make_float2(d.z, d.w);
            *(float2*)&Ws[nb][lr + 64][lq    ] = make_float2(e.x, e.y);
            *(float2*)&Ws[nb][lr + 64][lq + 2] = make_float2(e.z, e.w);
        }
    }
}

// =============================================================================
// Kernel 1: fused QKV projection with scatter epilogue into [b,h,s,d].
// =============================================================================
__global__ __launch_bounds__(256) void gemm_qkv_kernel(
    const float* __restrict__ X,
    const float* __restrict__ Wq,
    const float* __restrict__ Wk,
    const float* __restrict__ Wv)
{
    __shared__ __align__(16) float Xs[2][64][PAD_];
    __shared__ __align__(16) float Ws[2][96][PAD_];

    const int m0 = blockIdx.x * 64;
    const int cb = blockIdx.y;
    const float* __restrict__ W = (cb < 3) ? Wq : (cb < 6 ? Wk : Wv);
    float* dst = (cb < 3) ? g_q : (cb < 6 ? g_k : g_v);
    const int n0 = (cb % 3) * 96;
    const int tid = threadIdx.x;

    u64 acc[4][6];
#pragma unroll
    for (int i = 0; i < 4; i++)
#pragma unroll
        for (int j = 0; j < 6; j++) acc[i][j] = 0ULL;

    gemm_core<9>(X, W, m0, n0, 0, tid, Xs, Ws, acc);

    const int tr4 = (tid >> 4) * 4, tc = tid & 15;
#pragma unroll
    for (int i = 0; i < 4; i++) {
        int m = m0 + tr4 + i;
        int b = m >> 11, s = m & 2047;
#pragma unroll
        for (int j = 0; j < 6; j++) {
            float lo, hi; unpk2(acc[i][j], lo, hi);
            int c = n0 + tc + 16 * j;
            int h = c >> 4, d = c & 15;
            dst[(((size_t)(b * NH_ + h)) * S_ + s) * D_ + d] = lo + hi;
        }
    }
}

// =============================================================================
// Kernel 2: RoPE in-place; folds (1/sqrt(D)) * log2(e) into q.
// Two rotation pairs (d, d+1) per thread: same math order per element.
// =============================================================================
__global__ void rope_kernel()
{
    int idx = blockIdx.x * blockDim.x + threadIdx.x;
    const int total = 2 * B_ * NH_ * S_ * 4;         // 589,824 (2 pairs/thread)
    if (idx >= total) return;
    int d0 = (idx & 3) * 2;                          // d in {0,2,4,6}
    int s = (idx >> 2) & (S_ - 1);
    int v = idx >> 13;                               // 0..71
    bool isq = v < 36;
    float* base = (isq ? g_q : g_k) + (((size_t)(v % 36)) * S_ + s) * D_;
    float scale = isq ? QSCALE : 1.0f;
    float fs = (float)s;
#pragma unroll
    for (int u = 0; u < 2; u++) {
        int d = d0 + u;
        float f = fs * c_inv[d];
        float sn, cs;
        sincosf(f, &sn, &cs);
        float x0 = base[d];
        float x1 = base[d + 8];
        base[d]     = (x0 * cs - x1 * sn) * scale;
        base[d + 8] = (x1 * cs + x0 * sn) * scale;
    }
}

// =============================================================================
// Kernel 3: causal attention, split-K x4, double-buffered K/V,
// WARP-uniform mask specialization:
//   tile kt==2p   : warps 0-1 masked-A, warps 2-3 provably-unmasked A
//   tile kt==2p+1 : warps 0-1 A fully dead -> B-only; warps 2-3 masked-A
//   tile ntB-2    : warps 0-1 masked-B, warps 2-3 unmasked
//   tile ntB-1    : warps 0-1 SKIP ENTIRELY; warps 2-3 masked-B
// =============================================================================
template<bool BOTH, bool MASK>
__device__ __forceinline__ void attn_inner(
    const ulonglong2* __restrict__ Ks2, const ulonglong2* __restrict__ Vs2,
    const u64 (&qA)[8], const u64 (&qB)[8],
    u64 (&oA)[8], u64 (&oB)[8],
    float& lA, float& lB, int jthrA, int jthrB)
{
#pragma unroll 2
    for (int j = 0; j < 64; j++) {
        ulonglong2 k0 = Ks2[j * 4 + 0];
        ulonglong2 k1 = Ks2[j * 4 + 1];
        ulonglong2 k2 = Ks2[j * 4 + 2];
        ulonglong2 k3 = Ks2[j * 4 + 3];

        u64 b0 = mul2(qB[0], k0.x), b1 = mul2(qB[1], k0.y);
        b0 = fma2(qB[2], k1.x, b0); b1 = fma2(qB[3], k1.y, b1);
        b0 = fma2(qB[4], k2.x, b0); b1 = fma2(qB[5], k2.y, b1);
        b0 = fma2(qB[6], k3.x, b0); b1 = fma2(qB[7], k3.y, b1);
        u64 bs = add2(b0, b1);
        float blo, bhi; unpk2(bs, blo, bhi);
        float sB = blo + bhi;
        float pB;
        if (!BOTH && MASK) pB = (j <= jthrB) ? ex2(sB) : 0.0f;
        else               pB = ex2(sB);
        lB += pB;

        float pA = 0.0f;
        if (BOTH) {
            u64 a0 = mul2(qA[0], k0.x), a1 = mul2(qA[1], k0.y);
            a0 = fma2(qA[2], k1.x, a0); a1 = fma2(qA[3], k1.y, a1);
            a0 = fma2(qA[4], k2.x, a0); a1 = fma2(qA[5], k2.y, a1);
            a0 = fma2(qA[6], k3.x, a0); a1 = fma2(qA[7], k3.y, a1);
            u64 as = add2(a0, a1);
            float alo, ahi; unpk2(as, alo, ahi);
            float sA = alo + ahi;
            if (MASK) pA = (j <= jthrA) ? ex2(sA) : 0.0f;
            else      pA = ex2(sA);
            lA += pA;
        }

        ulonglong2 v0 = Vs2[j * 4 + 0];
        ulonglong2 v1 = Vs2[j * 4 + 1];
        ulonglong2 v2 = Vs2[j * 4 + 2];
        ulonglong2 v3 = Vs2[j * 4 + 3];

        u64 pB2 = pk2(pB, pB);
        oB[0] = fma2(pB2, v0.x, oB[0]); oB[1] = fma2(pB2, v0.y, oB[1]);
        oB[2] = fma2(pB2, v1.x, oB[2]); oB[3] = fma2(pB2, v1.y, oB[3]);
        oB[4] = fma2(pB2, v2.x, oB[4]); oB[5] = fma2(pB2, v2.y, oB[5]);
        oB[6] = fma2(pB2, v3.x, oB[6]); oB[7] = fma2(pB2, v3.y, oB[7]);
        if (BOTH) {
            u64 pA2 = pk2(pA, pA);
            oA[0] = fma2(pA2, v0.x, oA[0]); oA[1] = fma2(pA2, v0.y, oA[1]);
            oA[2] = fma2(pA2, v1.x, oA[2]); oA[3] = fma2(pA2, v1.y, oA[3]);
            oA[4] = fma2(pA2, v2.x, oA[4]); oA[5] = fma2(pA2, v2.y, oA[5]);
            oA[6] = fma2(pA2, v3.x, oA[6]); oA[7] = fma2(pA2, v3.y, oA[7]);
        }
    }
}

__global__ __launch_bounds__(128) void attn_kernel()
{
    __shared__ __align__(16) float Ks[2][64 * 16];
    __shared__ __align__(16) float Vs[2][64 * 16];

    const int bh   = blockIdx.y;                     // 0..35
    const int p    = blockIdx.x;                     // 0..7 (pair index)
    const int half = blockIdx.z;                     // 0..NSPLIT-1 (tile residue)
    const int tid  = threadIdx.x;
    const int wid  = tid >> 5;                       // warp 0..3
    const int qa = p * 128 + tid;                    // short query
    const int qb = (15 - p) * 128 + tid;             // long query
    const int ntA = 2 * p + 2;
    const int ntB = 32 - 2 * p;

    const float* qpa = g_q + ((size_t)bh * S_ + qa) * D_;
    const float* qpb = g_q + ((size_t)bh * S_ + qb) * D_;
    u64 qA[8], qB[8];
#pragma unroll
    for (int c = 0; c < 8; c++) {
        qA[c] = *(const u64*)(qpa + 2 * c);          // pre-scaled in rope
        qB[c] = *(const u64*)(qpb + 2 * c);
    }
    u64 oA[8], oB[8];
#pragma unroll
    for (int i = 0; i < 8; i++) { oA[i] = 0ULL; oB[i] = 0ULL; }
    float lA = 0.0f, lB = 0.0f;

    const float* kbase = g_k + (size_t)bh * S_ * D_;
    const float* vbase = g_v + (size_t)bh * S_ * D_;

    // ---- prologue: first tile into buffer 0 ---------------------------------
    {
        const float4* ks = (const float4*)(kbase + (size_t)half * 64 * D_);
        const float4* vs = (const float4*)(vbase + (size_t)half * 64 * D_);
        float4 ka = ks[tid], kb = ks[tid + 128];
        float4 va = vs[tid], vb = vs[tid + 128];
        ((float4*)Ks[0])[tid]       = ka;
        ((float4*)Ks[0])[tid + 128] = kb;
        ((float4*)Vs[0])[tid]       = va;
        ((float4*)Vs[0])[tid + 128] = vb;
    }

    int buf = 0;
    for (int kt = half; kt < ntB; kt += NSPLIT, buf ^= 1) {
        const int ktn = kt + NSPLIT;
        float4 nka, nkb, nva, nvb;
        const bool has_next = ktn < ntB;
        if (has_next) {
            const float4* ks = (const float4*)(kbase + (size_t)ktn * 64 * D_);
            const float4* vs = (const float4*)(vbase + (size_t)ktn * 64 * D_);
            nka = ks[tid]; nkb = ks[tid + 128];
            nva = vs[tid]; nvb = vs[tid + 128];
        }
        __syncthreads();   // buf fully written; prior compute on buf^1 done

        const ulonglong2* Ks2 = (const ulonglong2*)Ks[buf];
        const ulonglong2* Vs2 = (const ulonglong2*)Vs[buf];
        const int jthrA = qa - kt * 64;
        const int jthrB = qb - kt * 64;
        if (kt < ntA) {
            if (kt < 2 * p) {
                attn_inner<true, false>(Ks2, Vs2, qA, qB, oA, oB, lA, lB, jthrA, jthrB);
            } else if (kt == 2 * p) {
                // jthrA = tid: warps 2-3 fully unmasked (tid >= 64 > 63)
                if (wid >= 2)
                    attn_inner<true, false>(Ks2, Vs2, qA, qB, oA, oB, lA, lB, jthrA, jthrB);
                else
                    attn_inner<true, true >(Ks2, Vs2, qA, qB, oA, oB, lA, lB, jthrA, jthrB);
            } else { // kt == 2p+1: jthrA = tid-64: warps 0-1 A fully dead
                if (wid < 2)
                    attn_inner<false, false>(Ks2, Vs2, qA, qB, oA, oB, lA, lB, jthrA, jthrB);
                else
                    attn_inner<true,  true >(Ks2, Vs2, qA, qB, oA, oB, lA, lB, jthrA, jthrB);
            }
        } else {
            if (kt < ntB - 2) {
                attn_inner<false, false>(Ks2, Vs2, qA, qB, oA, oB, lA, lB, jthrA, jthrB);
            } else if (kt == ntB - 2) {
                // jthrB = tid: warps 2-3 fully unmasked
                if (wid >= 2)
                    attn_inner<false, false>(Ks2, Vs2, qA, qB, oA, oB, lA, lB, jthrA, jthrB);
                else
                    attn_inner<false, true >(Ks2, Vs2, qA, qB, oA, oB, lA, lB, jthrA, jthrB);
            } else { // kt == ntB-1: jthrB = tid-64: warps 0-1 fully masked -> skip
                if (wid >= 2)
                    attn_inner<false, true >(Ks2, Vs2, qA, qB, oA, oB, lA, lB, jthrA, jthrB);
            }
        }

        if (has_next) {
            const int nb = buf ^ 1;
            ((float4*)Ks[nb])[tid]       = nka;
            ((float4*)Ks[nb])[tid + 128] = nkb;
            ((float4*)Vs[nb])[tid]       = nva;
            ((float4*)Vs[nb])[tid + 128] = nvb;
        }
    }

    // ---- write partials as STG.128 (merge kernel combines residues) ---------
    const size_t ia = (size_t)half * PART_Q + (size_t)bh * S_ + qa;
    const size_t ib = (size_t)half * PART_Q + (size_t)bh * S_ + qb;
    ulonglong2* poa = (ulonglong2*)(g_po + ia * 16);
    ulonglong2* pob = (ulonglong2*)(g_po + ib * 16);
#pragma unroll
    for (int i = 0; i < 4; i++) {
        ulonglong2 va; va.x = oA[2 * i]; va.y = oA[2 * i + 1];
        ulonglong2 vb; vb.x = oB[2 * i]; vb.y = oB[2 * i + 1];
        poa[i] = va;
        pob[i] = vb;
    }
    g_pl[ia] = lA;
    g_pl[ib] = lB;
}

// Merge the NSPLIT residues: out = sum(o)/sum(l), scattered into g_ao.
// One thread per (query, 4-float chunk) for parallelism.
__global__ __launch_bounds__(256) void merge_attn_kernel()
{
    int idx = blockIdx.x * blockDim.x + threadIdx.x;  // PART_Q * 4
    if (idx >= PART_Q * 4) return;
    const int q = idx >> 2, c = idx & 3;
    float l = g_pl[q] + g_pl[PART_Q + q] + g_pl[2 * PART_Q + q] + g_pl[3 * PART_Q + q];
    const float inv = 1.0f / l;
    float4 a0 = *(const float4*)(g_po + ((size_t)q * 16) + c * 4);
    float4 a1 = *(const float4*)(g_po + (((size_t)PART_Q + q) * 16) + c * 4);
    float4 a2 = *(const float4*)(g_po + (((size_t)2 * PART_Q + q) * 16) + c * 4);
    float4 a3 = *(const float4*)(g_po + (((size_t)3 * PART_Q + q) * 16) + c * 4);
    float4 r;
    r.x = (a0.x + a1.x + a2.x + a3.x) * inv;
    r.y = (a0.y + a1.y + a2.y + a3.y) * inv;
    r.z = (a0.z + a1.z + a2.z + a3.z) * inv;
    r.w = (a0.w + a1.w + a2.w + a3.w) * inv;
    const int bh = q >> 11, s = q & 2047;
    const int b = bh / NH_, h = bh % NH_;
    *(float4*)(g_ao + ((size_t)(b * S_ + s)) * H_ + h * D_ + c * 4) = r;
}

// =============================================================================
// Kernel 4: output projection, split-K x3 -> partials; kernel 5 reduces.
// =============================================================================
__global__ __launch_bounds__(256) void gemm_out_kernel(
    const float* __restrict__ W)
{
    __shared__ __align__(16) float Xs[2][64][PAD_];
    __shared__ __align__(16) float Ws[2][96][PAD_];

    const int m0 = blockIdx.x * 64;
    const int n0 = blockIdx.y * 96;
    const int ks = blockIdx.z;
    const int tid = threadIdx.x;

    u64 acc[4][6];
#pragma unroll
    for (int i = 0; i < 4; i++)
#pragma unroll
        for (int j = 0; j < 6; j++) acc[i][j] = 0ULL;

    gemm_core<3>(g_ao, W, m0, n0, ks * 96, tid, Xs, Ws, acc);

    float* P = g_part + (size_t)ks * M_TOT * H_;
    const int tr4 = (tid >> 4) * 4, tc = tid & 15;
#pragma unroll
    for (int i = 0; i < 4; i++) {
        size_t m = m0 + tr4 + i;
#pragma unroll
        for (int j = 0; j < 6; j++) {
            float lo, hi; unpk2(acc[i][j], lo, hi);
            P[m * 288 + n0 + tc + 16 * j] = lo + hi;
        }
    }
}

__global__ __launch_bounds__(256) void reduce_out_kernel(float* __restrict__ Y)
{
    const int N4 = M_TOT * H_ / 4;
    int i = blockIdx.x * blockDim.x + threadIdx.x;
    if (i >= N4) return;
    const float4* P = (const float4*)g_part;
    float4 a = P[i], b = P[i + N4], c = P[i + 2 * N4];
    float4 r;
    r.x = a.x + b.x + c.x;
    r.y = a.y + b.y + c.y;
    r.z = a.z + b.z + c.z;
    r.w = a.w + b.w + c.w;
    ((float4*)Y)[i] = r;
}

// =============================================================================
extern "C" void kernel_launch(void* const* d_in, const int* in_sizes, int n_in,
                              void* d_out, int out_size)
{
    const float* hs = (const float*)d_in[0];
    const float* Wq = (const float*)d_in[1];
    const float* Wk = (const float*)d_in[2];
    const float* Wv = (const float*)d_in[3];
    const float* Wo = (const float*)d_in[4];
    float* out = (float*)d_out;

    gemm_qkv_kernel<<<dim3(64, 9), 256>>>(hs, Wq, Wk, Wv);

    const int rope_total = 2 * B_ * NH_ * S_ * 4;
    rope_kernel<<<(rope_total + 255) / 256, 256>>>();

    attn_kernel<<<dim3(8, 36, NSPLIT), 128>>>();
    merge_attn_kernel<<<(PART_Q * 4 + 255) / 256, 256>>>();

    gemm_out_kernel<<<dim3(64, 3, 3), 256>>>(Wo);
    reduce_out_kernel<<<(M_TOT * H_ / 4 + 255) / 256, 256>>>(out);
}